// round 16
// baseline (speedup 1.0000x reference)
#include <cuda_runtime.h>
#include <math.h>
#include <cmath>

#define NROWS 32
#define NCOLS 512
#define NTILES 16                 // 512 / 32
#define BLOCKS_X 34               // 272 half-jobs / 8 warps per block
#define TOTAL_BLOCKS (BLOCKS_X * NROWS)   // 1088
#define TSG 1024                  // g table size
#define G_MIN (-24.0f)
#define G_RANGE 64.0f             // g domain [-24, 40]
#define NB_TAU 8
#define NB_G 8
#define NB_W 6
#define W_FLOOR 0.001f
#define PDEG 8                    // polynomial coeff count (degree 7)
#define MAGIC 12582912.0f         // 1.5 * 2^23

// Constant linear map softplus(theta) -> monomial coeffs, host-computed.
struct FitMats {
    float bt[PDEG][NB_TAU];
    float bw[PDEG][NB_W];
};

// ---------------- device scratch (no allocations allowed) ----------------
__device__ float2 d_tab_g[TSG];                        // (g0, dg) lerp table
__device__ __align__(16) unsigned long long d_pk[PDEG]; // packed (tau, w+floor) coeffs
__device__ float2 d_rs[NROWS * NCOLS];                 // (r or NaN, normalized s)
__device__ float  d_part_sum[TOTAL_BLOCKS];
__device__ float  d_part_cnt[TOTAL_BLOCKS];
__device__ int    d_done;

__device__ __forceinline__ float fsp(float z) {
    return fmaxf(z, 0.0f) + __logf(1.0f + __expf(-fabsf(z)));
}

__device__ __forceinline__ unsigned long long pack2(float lo, float hi) {
    unsigned long long r;
    asm("mov.b64 %0, {%1, %2};" : "=l"(r) : "f"(lo), "f"(hi));
    return r;
}
__device__ __forceinline__ void unpack2(unsigned long long v, float& lo, float& hi) {
    asm("mov.b64 {%0, %1}, %2;" : "=f"(lo), "=f"(hi) : "l"(v));
}
__device__ __forceinline__ unsigned long long ffma2(
    unsigned long long a, unsigned long long b, unsigned long long c) {
    unsigned long long d;
    asm("fma.rn.f32x2 %0, %1, %2, %3;" : "=l"(d) : "l"(a), "l"(b), "l"(c));
    return d;
}

// ---------------- kernel A: g table + normalization + packed coeffs ---------
__global__ void __launch_bounds__(128) setup_kernel(
    const float* __restrict__ pred, const float* __restrict__ tg,
    const float* __restrict__ th_tau, const float* __restrict__ th_g,
    const float* __restrict__ th_w, FitMats P)
{
    int tid = threadIdx.x;
    int bx  = blockIdx.x;
    if (bx < 8) {
        int i = bx * 128 + tid;   // 0..1023
        float cg[NB_G];
#pragma unroll
        for (int u = 0; u < NB_G; u++) cg[u] = fsp(th_g[u]);
        float h = G_RANGE / (float)(TSG - 1);
        float x = G_MIN + (float)i * h;
        float v0 = 0.f, v1 = 0.f;
#pragma unroll
        for (int u = 0; u < NB_G; u++) {
            float sl = 0.5f + 3.5f * (float)u / (float)(NB_G - 1);
            float bi = -2.0f + 4.0f * (float)u / (float)(NB_G - 1);
            v0 += cg[u] * fsp(fmaf(x,     sl, bi));
            v1 += cg[u] * fsp(fmaf(x + h, sl, bi));
        }
        d_tab_g[i] = make_float2(v0, v1 - v0);
    } else if (bx < 16) {
        // one warp per row: masked mean/var normalization, write d_rs
        int w = (bx - 8) * 4 + (tid >> 5), lane = tid & 31;
        const float* p = pred + w * NCOLS;
        const float* t = tg   + w * NCOLS;
        float lp[16], lt[16]; bool lm[16];
        float sum = 0.0f, ssq = 0.0f, cnt = 0.0f;
#pragma unroll
        for (int u = 0; u < 16; u++) {
            float tv = t[lane + 32 * u];
            bool  m  = fabsf(tv + 1.0f) > 1.00001e-5f;   // ~jnp.isclose(t,-1) negated
            float pv = p[lane + 32 * u];
            lp[u] = pv; lt[u] = tv; lm[u] = m;
            sum += m ? pv : 0.0f;
            ssq += m ? pv * pv : 0.0f;
            cnt += m ? 1.0f : 0.0f;
        }
#pragma unroll
        for (int o = 16; o; o >>= 1) {
            sum += __shfl_xor_sync(0xffffffffu, sum, o);
            ssq += __shfl_xor_sync(0xffffffffu, ssq, o);
            cnt += __shfl_xor_sync(0xffffffffu, cnt, o);
        }
        float denom = fmaxf(cnt, 1.0f);
        float mean  = sum / denom;
        float var   = ssq / denom - mean * mean;
        float inv   = rsqrtf(var + 1e-6f);
        const float qnan = __int_as_float(0x7fffffff);
#pragma unroll
        for (int u = 0; u < 16; u++)
            d_rs[w * NCOLS + lane + 32 * u] =
                make_float2(lm[u] ? lt[u] : qnan, (lp[u] - mean) * inv);
    } else if (tid < PDEG) {
        // packed poly coeffs; W_FLOOR folded into w's constant term
        float st = 0.0f, sw = 0.0f;
#pragma unroll
        for (int i = 0; i < NB_TAU; i++) st += fsp(th_tau[i]) * P.bt[tid][i];
#pragma unroll
        for (int i = 0; i < NB_W; i++)  sw += fsp(th_w[i]) * P.bw[tid][i];
        if (tid == 0) sw += W_FLOOR;
        d_pk[tid] = ((unsigned long long)__float_as_uint(sw) << 32) |
                    (unsigned long long)__float_as_uint(st);
    }
}

// ---------------- kernel B: half-tile pair loop, all-smem, fused final ------
__global__ void __launch_bounds__(256, 5) pair_kernel(float* __restrict__ out) {
    __shared__ float2 sh_g[TSG];       // 8 KB — the one scattered access
    __shared__ float2 sh_rs[NCOLS];    // 4 KB — this row (broadcast reads)
    __shared__ float  red_f[8];
    __shared__ float  red_c[8];
    __shared__ int    sh_last;
    __shared__ float  s_num[32];
    __shared__ float  s_val[32];

    int tid  = threadIdx.x;
    int b    = blockIdx.y;
    int lane = tid & 31, warp = tid >> 5;

    // ---- slim prologue: 12 KB copy (3 float4/thread) + coeff regs ----
    {
        const float4* sg = (const float4*)d_tab_g;            float4* dg = (float4*)sh_g;
        const float4* sr = (const float4*)(d_rs + b * NCOLS); float4* dr = (float4*)sh_rs;
        dg[tid] = sg[tid]; dg[tid + 256] = sg[tid + 256];
        dr[tid] = sr[tid];
    }
    unsigned long long pk[PDEG];
    {
        const ulonglong2* pp = (const ulonglong2*)d_pk;
#pragma unroll
        for (int u = 0; u < PDEG / 2; u++) {
            ulonglong2 q = __ldg(&pp[u]);
            pk[2 * u] = q.x; pk[2 * u + 1] = q.y;
        }
    }

    // ---- job decode: jb2 in [0,272) -> tile in [0,136) + half ----
    int jb2  = blockIdx.x * 8 + warp;
    int tile = jb2 >> 1;
    int half = jb2 & 1;
    // triangular decode via sqrt + fixup: 0 <= ti <= tj < 16
    float sq = sqrtf((float)(1089 - 8 * tile));
    int ti = (int)((33.0f - sq) * 0.5f);
    int base = (ti * (33 - ti)) >> 1;
    if (tile < base) { ti -= 1; base = (ti * (33 - ti)) >> 1; }
    else { int len = NTILES - ti; if (tile - base >= len) { base += len; ti += 1; } }
    int tj  = ti + (tile - base);
    int lim = (ti == tj) ? lane : 32;
    int iibase = half * 16;

    const float inv_hg = (float)(TSG - 1) / G_RANGE;
    const float c0     = -G_MIN * inv_hg;

    __syncthreads();   // tables + row ready
    float2 pj = sh_rs[tj * 32 + lane];            // register-resident j side

    float acc = 0.0f; int cnt = 0;
#pragma unroll
    for (int u = 0; u < 16; u++) {
        int ii = iibase + u;
        float2 pi = sh_rs[ii + 16 * (half == 0 ? 0 : 0) + (ti << 5) - iibase + iibase]; // placeholder
        pi = sh_rs[(ti << 5) + ii];               // uniform LDS.64 broadcast
        float dr = pi.x - pj.x;
        float ds = pi.y - pj.y;
        float adr = fabsf(dr);
        bool keep = (adr > 0.0f) & (ii < lim);    // false for ties and NaN
        // t * ds via sign-bit transfer
        float tds = __int_as_float(__float_as_int(ds) ^
                                   (__float_as_int(dr) & 0x80000000));
        float t = fminf(adr, 1.0f);               // fminf(NaN,1)=1 -> safe
        // tau & (w + floor) via ONE packed f32x2 Horner chain (7 FFMA2)
        unsigned long long tt = pack2(t, t);
        unsigned long long h  = pk[PDEG - 1];
#pragma unroll
        for (int v = PDEG - 2; v >= 0; v--) h = ffma2(h, tt, pk[v]);
        float tau, w;
        unpack2(h, tau, w);
        float m  = tau - tds;
        float pg = fmaxf(fmaf(m, inv_hg, c0), 0.0f);   // fmaxf(NaN,0)=0 -> safe
        // magic-number round: no F2I/I2F in the chain
        float y  = pg + MAGIC;
        int   ig = min(__float_as_int(y) & 0xFFFF, TSG - 2);
        float fg = pg - (y - MAGIC);              // in [-0.5,0.5]; same-order lerp err
        float2 eg = sh_g[ig];                     // LDS.64 gather
        float g  = fmaf(fg, eg.y, eg.x);
        if (keep) { acc += g * w; cnt += 1; }
    }

#pragma unroll
    for (int o = 16; o; o >>= 1) {
        acc += __shfl_xor_sync(0xffffffffu, acc, o);
        cnt += __shfl_xor_sync(0xffffffffu, cnt, o);
    }
    if (lane == 0) { red_f[warp] = acc; red_c[warp] = (float)cnt; }
    __syncthreads();
    if (tid == 0) {
        float bs = 0.0f, bc = 0.0f;
#pragma unroll
        for (int u = 0; u < 8; u++) { bs += red_f[u]; bc += red_c[u]; }
        int slot = b * BLOCKS_X + blockIdx.x;
        d_part_sum[slot] = bs;
        d_part_cnt[slot] = bc;
        __threadfence();
        int old = atomicAdd(&d_done, 1);
        sh_last = (old == TOTAL_BLOCKS - 1) ? 1 : 0;
    }
    __syncthreads();

    // ---- last block: final reduction over 1088 partials ----
    if (sh_last) {
        __threadfence();
        volatile float* vs = d_part_sum;
        volatile float* vc = d_part_cnt;
        int row = tid >> 3;            // 32 rows x 8 lanes
        int sub = tid & 7;
        int bse = row * BLOCKS_X;
        float ps = 0.0f, pc = 0.0f;
        for (int k = sub; k < BLOCKS_X; k += 8) { ps += vs[bse + k]; pc += vc[bse + k]; }
#pragma unroll
        for (int o = 4; o; o >>= 1) {
            ps += __shfl_xor_sync(0xffffffffu, ps, o);
            pc += __shfl_xor_sync(0xffffffffu, pc, o);
        }
        if (sub == 0) {
            float denom = fmaxf(pc, 1.0f);
            float rl    = ps / denom;
            float valid = (pc > 0.0f) ? 1.0f : 0.0f;
            s_num[row] = rl * valid;
            s_val[row] = valid;
        }
        __syncthreads();
        if (tid < 32) {
            float n = s_num[tid], v = s_val[tid];
#pragma unroll
            for (int o = 16; o; o >>= 1) {
                n += __shfl_xor_sync(0xffffffffu, n, o);
                v += __shfl_xor_sync(0xffffffffu, v, o);
            }
            if (tid == 0) {
                out[0] = n / fmaxf(v, 1.0f);
                d_done = 0;            // reset for next graph replay
            }
        }
    }
}

// ---------------- host-side fit matrix construction --------------------------
// Monomial coeffs of shifted Chebyshev T*_n(x)=T_n(2x-1), n<8: exact integers.
static const double h_cheb_mono[PDEG][PDEG] = {
    {  1,    0,     0,      0,       0,       0,        0,        0},
    { -1,    2,     0,      0,       0,       0,        0,        0},
    {  1,   -8,     8,      0,       0,       0,        0,        0},
    { -1,   18,   -48,     32,       0,       0,        0,        0},
    {  1,  -32,   160,   -256,     128,       0,        0,        0},
    { -1,   50,  -400,   1120,   -1280,     512,        0,        0},
    {  1,  -72,   840,  -3584,    6912,   -6144,     2048,        0},
    { -1,   98, -1568,   9408,  -26880,   39424,   -28672,     8192}
};

static void host_fit_basis(double sl, double bi, bool is_sigmoid, double* bcol) {
    double xs[PDEG], f[PDEG];
    for (int k = 0; k < PDEG; k++) {
        xs[k] = 0.5 + 0.5 * cos(M_PI * (k + 0.5) / PDEG);
        double z = xs[k] * sl + bi;
        f[k] = is_sigmoid ? 1.0 / (1.0 + exp(-z))
                          : ((z > 0.0) ? z + log1p(exp(-z)) : log1p(exp(z)));
    }
    double a[PDEG];
    for (int n = 0; n < PDEG; n++) {
        double s = 0.0;
        for (int k = 0; k < PDEG; k++)
            s += f[k] * cos(M_PI * n * (2 * k + 1) / (2.0 * PDEG));
        a[n] = s * ((n == 0) ? (1.0 / PDEG) : (2.0 / PDEG));
    }
    for (int m = 0; m < PDEG; m++) {
        double s = 0.0;
        for (int n = 0; n < PDEG; n++) s += a[n] * h_cheb_mono[n][m];
        bcol[m] = s;
    }
}

static void build_fit_mats(FitMats* F) {
    double col[PDEG];
    for (int i = 0; i < NB_TAU; i++) {
        double sl = 0.5 + 3.5 * (double)i / (double)(NB_TAU - 1);
        double bi = -2.0 + 4.0 * (double)i / (double)(NB_TAU - 1);
        host_fit_basis(sl, bi, false, col);
        for (int m = 0; m < PDEG; m++) F->bt[m][i] = (float)col[m];
    }
    for (int i = 0; i < NB_W; i++) {
        double sl = 0.5 + 3.5 * (double)i / (double)(NB_W - 1);
        double bi = -2.0 + 4.0 * (double)i / (double)(NB_W - 1);
        host_fit_basis(sl, bi, true, col);
        for (int m = 0; m < PDEG; m++) F->bw[m][i] = (float)col[m];
    }
}

// ---------------- launch ----------------
extern "C" void kernel_launch(void* const* d_in, const int* in_sizes, int n_in,
                              void* d_out, int out_size) {
    const float* pred   = (const float*)d_in[0];
    const float* tg     = (const float*)d_in[1];
    const float* th_tau = (const float*)d_in[2];
    const float* th_g   = (const float*)d_in[3];
    const float* th_w   = (const float*)d_in[4];

    FitMats F;                 // host-computed, deterministic; baked into graph
    build_fit_mats(&F);

    setup_kernel<<<17, 128>>>(pred, tg, th_tau, th_g, th_w, F);
    dim3 grid(BLOCKS_X, NROWS);
    pair_kernel<<<grid, 256>>>((float*)d_out);
}

// round 17
// speedup vs baseline: 1.0210x; 1.0210x over previous
#include <cuda_runtime.h>
#include <math.h>
#include <cmath>

#define NROWS 32
#define NCOLS 512
#define NTILES 16                 // 512 / 32
#define BLOCKS_X 17               // 272 half-jobs / 16 warps per block
#define TOTAL_BLOCKS (BLOCKS_X * NROWS)   // 544
#define TSG 512                   // g table size
#define G_MIN (-24.0f)
#define G_RANGE 64.0f             // g domain [-24, 40]
#define NB_TAU 8
#define NB_G 8
#define NB_W 6
#define W_FLOOR 0.001f
#define PDEG 8                    // polynomial coeff count (degree 7)
#define MAGIC 12582912.0f         // 1.5 * 2^23

// Constant linear map softplus(theta) -> monomial coeffs, host-computed.
struct FitMats {
    float bt[PDEG][NB_TAU];
    float bw[PDEG][NB_W];
};

// ---------------- device scratch (no allocations allowed) ----------------
__device__ float2 d_tab_g[TSG];                        // (g0, dg) lerp table
__device__ __align__(16) unsigned long long d_pk[PDEG]; // packed (tau, w+floor) coeffs
__device__ float2 d_rs[NROWS * NCOLS];                 // (r or NaN, normalized s)
__device__ float  d_part_sum[TOTAL_BLOCKS];
__device__ float  d_part_cnt[TOTAL_BLOCKS];
__device__ int    d_done;

__device__ __forceinline__ float fsp(float z) {
    return fmaxf(z, 0.0f) + __logf(1.0f + __expf(-fabsf(z)));
}

__device__ __forceinline__ unsigned long long pack2(float lo, float hi) {
    unsigned long long r;
    asm("mov.b64 %0, {%1, %2};" : "=l"(r) : "f"(lo), "f"(hi));
    return r;
}
__device__ __forceinline__ void unpack2(unsigned long long v, float& lo, float& hi) {
    asm("mov.b64 {%0, %1}, %2;" : "=f"(lo), "=f"(hi) : "l"(v));
}
__device__ __forceinline__ unsigned long long ffma2(
    unsigned long long a, unsigned long long b, unsigned long long c) {
    unsigned long long d;
    asm("fma.rn.f32x2 %0, %1, %2, %3;" : "=l"(d) : "l"(a), "l"(b), "l"(c));
    return d;
}

// ---------------- kernel A: g table + normalization + packed coeffs ---------
// blocks 0..3 : g lerp table (128 entries each, single-eval + neighbor delta)
// blocks 4..11: row normalization (4 rows per block, 1 warp per row)
// block 12    : packed poly coeffs
__global__ void __launch_bounds__(128) setup_kernel(
    const float* __restrict__ pred, const float* __restrict__ tg,
    const float* __restrict__ th_tau, const float* __restrict__ th_g,
    const float* __restrict__ th_w, FitMats P)
{
    __shared__ float sh_v[129];
    int tid = threadIdx.x;
    int bx  = blockIdx.x;
    if (bx < 4) {
        float cg[NB_G];
#pragma unroll
        for (int u = 0; u < NB_G; u++) cg[u] = fsp(th_g[u]);
        const float h = G_RANGE / (float)(TSG - 1);
        int i0 = bx * 128;
        // evaluate g once per entry; delta from the neighbor (halves eval work)
        {
            float x = G_MIN + (float)(i0 + tid) * h;
            float v = 0.f;
#pragma unroll
            for (int u = 0; u < NB_G; u++) {
                float sl = 0.5f + 3.5f * (float)u / (float)(NB_G - 1);
                float bi = -2.0f + 4.0f * (float)u / (float)(NB_G - 1);
                v += cg[u] * fsp(fmaf(x, sl, bi));
            }
            sh_v[tid] = v;
        }
        if (tid == 0) {
            float x = G_MIN + (float)(i0 + 128) * h;
            float v = 0.f;
#pragma unroll
            for (int u = 0; u < NB_G; u++) {
                float sl = 0.5f + 3.5f * (float)u / (float)(NB_G - 1);
                float bi = -2.0f + 4.0f * (float)u / (float)(NB_G - 1);
                v += cg[u] * fsp(fmaf(x, sl, bi));
            }
            sh_v[128] = v;
        }
        __syncthreads();
        d_tab_g[i0 + tid] = make_float2(sh_v[tid], sh_v[tid + 1] - sh_v[tid]);
    } else if (bx < 12) {
        // one warp per row: masked mean/var normalization, write d_rs
        int w = (bx - 4) * 4 + (tid >> 5), lane = tid & 31;
        const float* p = pred + w * NCOLS;
        const float* t = tg   + w * NCOLS;
        float lp[16], lt[16]; bool lm[16];
        float sum = 0.0f, ssq = 0.0f, cnt = 0.0f;
#pragma unroll
        for (int u = 0; u < 16; u++) {
            float tv = t[lane + 32 * u];
            bool  m  = fabsf(tv + 1.0f) > 1.00001e-5f;   // ~jnp.isclose(t,-1) negated
            float pv = p[lane + 32 * u];
            lp[u] = pv; lt[u] = tv; lm[u] = m;
            sum += m ? pv : 0.0f;
            ssq += m ? pv * pv : 0.0f;
            cnt += m ? 1.0f : 0.0f;
        }
#pragma unroll
        for (int o = 16; o; o >>= 1) {
            sum += __shfl_xor_sync(0xffffffffu, sum, o);
            ssq += __shfl_xor_sync(0xffffffffu, ssq, o);
            cnt += __shfl_xor_sync(0xffffffffu, cnt, o);
        }
        float denom = fmaxf(cnt, 1.0f);
        float mean  = sum / denom;
        float var   = ssq / denom - mean * mean;
        float inv   = rsqrtf(var + 1e-6f);
        const float qnan = __int_as_float(0x7fffffff);
#pragma unroll
        for (int u = 0; u < 16; u++)
            d_rs[w * NCOLS + lane + 32 * u] =
                make_float2(lm[u] ? lt[u] : qnan, (lp[u] - mean) * inv);
    } else if (tid < PDEG) {
        // packed poly coeffs; W_FLOOR folded into w's constant term
        float st = 0.0f, sw = 0.0f;
#pragma unroll
        for (int i = 0; i < NB_TAU; i++) st += fsp(th_tau[i]) * P.bt[tid][i];
#pragma unroll
        for (int i = 0; i < NB_W; i++)  sw += fsp(th_w[i]) * P.bw[tid][i];
        if (tid == 0) sw += W_FLOOR;
        d_pk[tid] = ((unsigned long long)__float_as_uint(sw) << 32) |
                    (unsigned long long)__float_as_uint(st);
    }
}

// ---------------- kernel B: 16-warp blocks, half-tile jobs, fused final -----
__global__ void __launch_bounds__(512, 2) pair_kernel(float* __restrict__ out) {
    __shared__ float2 sh_g[TSG];       // 4 KB — the one scattered access
    __shared__ float2 sh_rs[NCOLS];    // 4 KB — this row (broadcast reads)
    __shared__ float  red_f[16];
    __shared__ float  red_c[16];
    __shared__ int    sh_last;
    __shared__ float  s_num[32];
    __shared__ float  s_val[32];

    int tid  = threadIdx.x;
    int b    = blockIdx.y;
    int lane = tid & 31, warp = tid >> 5;

    // ---- prologue: exactly ONE float4 per thread (4KB table + 4KB row) ----
    if (tid < 256) {
        ((float4*)sh_g)[tid] = ((const float4*)d_tab_g)[tid];
    } else {
        ((float4*)sh_rs)[tid - 256] = ((const float4*)(d_rs + b * NCOLS))[tid - 256];
    }
    unsigned long long pk[PDEG];
    {
        const ulonglong2* pp = (const ulonglong2*)d_pk;
#pragma unroll
        for (int u = 0; u < PDEG / 2; u++) {
            ulonglong2 q = __ldg(&pp[u]);
            pk[2 * u] = q.x; pk[2 * u + 1] = q.y;
        }
    }

    // ---- job decode: jb2 in [0,272) -> tile in [0,136) + half ----
    int jb2  = blockIdx.x * 16 + warp;
    int tile = jb2 >> 1;
    int half = jb2 & 1;
    // triangular decode via sqrt + fixup: 0 <= ti <= tj < 16
    float sq = sqrtf((float)(1089 - 8 * tile));
    int ti = (int)((33.0f - sq) * 0.5f);
    int base = (ti * (33 - ti)) >> 1;
    if (tile < base) { ti -= 1; base = (ti * (33 - ti)) >> 1; }
    else { int len = NTILES - ti; if (tile - base >= len) { base += len; ti += 1; } }
    int tj  = ti + (tile - base);
    int lim = (ti == tj) ? lane : 32;
    int iibase = half * 16;
    int ibase  = (ti << 5);

    const float inv_hg = (float)(TSG - 1) / G_RANGE;
    const float c0     = -G_MIN * inv_hg;

    __syncthreads();   // tables + row ready
    float2 pj = sh_rs[tj * 32 + lane];            // register-resident j side

    float acc = 0.0f; int cnt = 0;
#pragma unroll
    for (int u = 0; u < 16; u++) {
        int ii = iibase + u;
        float2 pi = sh_rs[ibase + ii];            // uniform LDS.64 broadcast
        float dr = pi.x - pj.x;
        float ds = pi.y - pj.y;
        float adr = fabsf(dr);
        bool keep = (adr > 0.0f) & (ii < lim);    // false for ties and NaN
        // t * ds via sign-bit transfer
        float tds = __int_as_float(__float_as_int(ds) ^
                                   (__float_as_int(dr) & 0x80000000));
        float t = fminf(adr, 1.0f);               // fminf(NaN,1)=1 -> safe
        // tau & (w + floor) via ONE packed f32x2 Horner chain (7 FFMA2)
        unsigned long long tt = pack2(t, t);
        unsigned long long h  = pk[PDEG - 1];
#pragma unroll
        for (int v = PDEG - 2; v >= 0; v--) h = ffma2(h, tt, pk[v]);
        float tau, w;
        unpack2(h, tau, w);
        float m  = tau - tds;
        float pg = fmaxf(fmaf(m, inv_hg, c0), 0.0f);   // fmaxf(NaN,0)=0 -> safe
        // magic-number round: no F2I/I2F in the chain
        float y  = pg + MAGIC;
        int   ig = min(__float_as_int(y) & 0xFFFF, TSG - 2);
        float fg = pg - (y - MAGIC);              // in [-0.5,0.5]; same-order lerp err
        float2 eg = sh_g[ig];                     // LDS.64 gather
        float g  = fmaf(fg, eg.y, eg.x);
        if (keep) { acc += g * w; cnt += 1; }
    }

#pragma unroll
    for (int o = 16; o; o >>= 1) {
        acc += __shfl_xor_sync(0xffffffffu, acc, o);
        cnt += __shfl_xor_sync(0xffffffffu, cnt, o);
    }
    if (lane == 0) { red_f[warp] = acc; red_c[warp] = (float)cnt; }
    __syncthreads();
    if (tid == 0) {
        float bs = 0.0f, bc = 0.0f;
#pragma unroll
        for (int u = 0; u < 16; u++) { bs += red_f[u]; bc += red_c[u]; }
        int slot = b * BLOCKS_X + blockIdx.x;
        d_part_sum[slot] = bs;
        d_part_cnt[slot] = bc;
        __threadfence();
        int old = atomicAdd(&d_done, 1);
        sh_last = (old == TOTAL_BLOCKS - 1) ? 1 : 0;
    }
    __syncthreads();

    // ---- last block: final reduction over 544 partials ----
    if (sh_last) {
        __threadfence();
        volatile float* vs = d_part_sum;
        volatile float* vc = d_part_cnt;
        int row = tid >> 4;            // 32 rows x 16 lanes (tid < 512)
        int sub = tid & 15;
        int bse = row * BLOCKS_X;
        float ps = 0.0f, pc = 0.0f;
        for (int k = sub; k < BLOCKS_X; k += 16) { ps += vs[bse + k]; pc += vc[bse + k]; }
#pragma unroll
        for (int o = 8; o; o >>= 1) {
            ps += __shfl_xor_sync(0xffffffffu, ps, o);
            pc += __shfl_xor_sync(0xffffffffu, pc, o);
        }
        if (sub == 0) {
            float denom = fmaxf(pc, 1.0f);
            float rl    = ps / denom;
            float valid = (pc > 0.0f) ? 1.0f : 0.0f;
            s_num[row] = rl * valid;
            s_val[row] = valid;
        }
        __syncthreads();
        if (tid < 32) {
            float n = s_num[tid], v = s_val[tid];
#pragma unroll
            for (int o = 16; o; o >>= 1) {
                n += __shfl_xor_sync(0xffffffffu, n, o);
                v += __shfl_xor_sync(0xffffffffu, v, o);
            }
            if (tid == 0) {
                out[0] = n / fmaxf(v, 1.0f);
                d_done = 0;            // reset for next graph replay
            }
        }
    }
}

// ---------------- host-side fit matrix construction --------------------------
// Monomial coeffs of shifted Chebyshev T*_n(x)=T_n(2x-1), n<8: exact integers.
static const double h_cheb_mono[PDEG][PDEG] = {
    {  1,    0,     0,      0,       0,       0,        0,        0},
    { -1,    2,     0,      0,       0,       0,        0,        0},
    {  1,   -8,     8,      0,       0,       0,        0,        0},
    { -1,   18,   -48,     32,       0,       0,        0,        0},
    {  1,  -32,   160,   -256,     128,       0,        0,        0},
    { -1,   50,  -400,   1120,   -1280,     512,        0,        0},
    {  1,  -72,   840,  -3584,    6912,   -6144,     2048,        0},
    { -1,   98, -1568,   9408,  -26880,   39424,   -28672,     8192}
};

static void host_fit_basis(double sl, double bi, bool is_sigmoid, double* bcol) {
    double xs[PDEG], f[PDEG];
    for (int k = 0; k < PDEG; k++) {
        xs[k] = 0.5 + 0.5 * cos(M_PI * (k + 0.5) / PDEG);
        double z = xs[k] * sl + bi;
        f[k] = is_sigmoid ? 1.0 / (1.0 + exp(-z))
                          : ((z > 0.0) ? z + log1p(exp(-z)) : log1p(exp(z)));
    }
    double a[PDEG];
    for (int n = 0; n < PDEG; n++) {
        double s = 0.0;
        for (int k = 0; k < PDEG; k++)
            s += f[k] * cos(M_PI * n * (2 * k + 1) / (2.0 * PDEG));
        a[n] = s * ((n == 0) ? (1.0 / PDEG) : (2.0 / PDEG));
    }
    for (int m = 0; m < PDEG; m++) {
        double s = 0.0;
        for (int n = 0; n < PDEG; n++) s += a[n] * h_cheb_mono[n][m];
        bcol[m] = s;
    }
}

static void build_fit_mats(FitMats* F) {
    double col[PDEG];
    for (int i = 0; i < NB_TAU; i++) {
        double sl = 0.5 + 3.5 * (double)i / (double)(NB_TAU - 1);
        double bi = -2.0 + 4.0 * (double)i / (double)(NB_TAU - 1);
        host_fit_basis(sl, bi, false, col);
        for (int m = 0; m < PDEG; m++) F->bt[m][i] = (float)col[m];
    }
    for (int i = 0; i < NB_W; i++) {
        double sl = 0.5 + 3.5 * (double)i / (double)(NB_W - 1);
        double bi = -2.0 + 4.0 * (double)i / (double)(NB_W - 1);
        host_fit_basis(sl, bi, true, col);
        for (int m = 0; m < PDEG; m++) F->bw[m][i] = (float)col[m];
    }
}

// ---------------- launch ----------------
extern "C" void kernel_launch(void* const* d_in, const int* in_sizes, int n_in,
                              void* d_out, int out_size) {
    const float* pred   = (const float*)d_in[0];
    const float* tg     = (const float*)d_in[1];
    const float* th_tau = (const float*)d_in[2];
    const float* th_g   = (const float*)d_in[3];
    const float* th_w   = (const float*)d_in[4];

    FitMats F;                 // host-computed, deterministic; baked into graph
    build_fit_mats(&F);

    setup_kernel<<<13, 128>>>(pred, tg, th_tau, th_g, th_w, F);
    dim3 grid(BLOCKS_X, NROWS);
    pair_kernel<<<grid, 512>>>((float*)d_out);
}